// round 1
// baseline (speedup 1.0000x reference)
#include <cuda_runtime.h>
#include <cuda_bf16.h>

// Per-batch partial results: total pair loss and pair count, in double.
// Sized generously (problem has B=256).
__device__ double g_total[1024];
__device__ double g_count[1024];

static constexpr float CX = 0.5f;

__device__ __forceinline__ float warp_red(float v) {
#pragma unroll
    for (int o = 16; o > 0; o >>= 1)
        v += __shfl_down_sync(0xFFFFFFFFu, v, o);
    return v;
}

// One block per batch. N = 512 points, 256 threads -> 2 points/thread.
__global__ void __launch_bounds__(256)
symc_partial_kernel(const float2* __restrict__ kp,
                    const int* __restrict__ cls,
                    int N) {
    const int b = blockIdx.x;
    const int t = threadIdx.x;
    const long base = (long)b * N;

    // 3 symmetric classes x 5 moments: m, Su, Su2, Sy, Sy2
    float m0 = 0.f, su0 = 0.f, sq0 = 0.f, sy0 = 0.f, sz0 = 0.f;
    float m1 = 0.f, su1 = 0.f, sq1 = 0.f, sy1 = 0.f, sz1 = 0.f;
    float m2 = 0.f, su2 = 0.f, sq2 = 0.f, sy2 = 0.f, sz2 = 0.f;

    for (int i = t; i < N; i += blockDim.x) {
        float2 p = kp[base + i];
        int c = cls[base + i];
        float u = p.x - CX;
        float uu = u * u;
        float y = p.y;
        float yy = y * y;
        if (c == 0) { m0 += 1.f; su0 += u; sq0 += uu; sy0 += y; sz0 += yy; }
        else if (c == 1) { m1 += 1.f; su1 += u; sq1 += uu; sy1 += y; sz1 += yy; }
        else if (c == 2) { m2 += 1.f; su2 += u; sq2 += uu; sy2 += y; sz2 += yy; }
    }

    // Warp reduction of all 15 accumulators
    m0 = warp_red(m0); su0 = warp_red(su0); sq0 = warp_red(sq0); sy0 = warp_red(sy0); sz0 = warp_red(sz0);
    m1 = warp_red(m1); su1 = warp_red(su1); sq1 = warp_red(sq1); sy1 = warp_red(sy1); sz1 = warp_red(sz1);
    m2 = warp_red(m2); su2 = warp_red(su2); sq2 = warp_red(sq2); sy2 = warp_red(sy2); sz2 = warp_red(sz2);

    __shared__ float s[8][15];
    const int wid = t >> 5, lid = t & 31;
    if (lid == 0) {
        s[wid][0] = m0;  s[wid][1] = su0;  s[wid][2] = sq0;  s[wid][3] = sy0;  s[wid][4] = sz0;
        s[wid][5] = m1;  s[wid][6] = su1;  s[wid][7] = sq1;  s[wid][8] = sy1;  s[wid][9] = sz1;
        s[wid][10] = m2; s[wid][11] = su2; s[wid][12] = sq2; s[wid][13] = sy2; s[wid][14] = sz2;
    }
    __syncthreads();

    if (t == 0) {
        double total = 0.0, cnt = 0.0;
#pragma unroll
        for (int c = 0; c < 3; c++) {
            double m = 0.0, Su = 0.0, Su2 = 0.0, Sy = 0.0, Sy2 = 0.0;
#pragma unroll
            for (int w = 0; w < 8; w++) {
                m   += (double)s[w][c * 5 + 0];
                Su  += (double)s[w][c * 5 + 1];
                Su2 += (double)s[w][c * 5 + 2];
                Sy  += (double)s[w][c * 5 + 3];
                Sy2 += (double)s[w][c * 5 + 4];
            }
            // sum_{i<j} (u_i+u_j)^2 = (m-2)*Su2 + Su^2
            // sum_{i<j} (y_i-y_j)^2 = m*Sy2 - Sy^2
            total += (m - 2.0) * Su2 + Su * Su + m * Sy2 - Sy * Sy;
            cnt += m * (m - 1.0) * 0.5;
        }
        g_total[b] = total;
        g_count[b] = cnt;
    }
}

// One block reduces B per-batch partials and writes the scalar mean.
__global__ void __launch_bounds__(256)
symc_finalize_kernel(float* __restrict__ out, int B) {
    const int t = threadIdx.x;
    double tot = 0.0, cnt = 0.0;
    for (int b = t; b < B; b += 256) {
        tot += g_total[b];
        cnt += g_count[b];
    }
#pragma unroll
    for (int o = 16; o > 0; o >>= 1) {
        tot += __shfl_down_sync(0xFFFFFFFFu, tot, o);
        cnt += __shfl_down_sync(0xFFFFFFFFu, cnt, o);
    }
    __shared__ double st[8], sc[8];
    const int wid = t >> 5, lid = t & 31;
    if (lid == 0) { st[wid] = tot; sc[wid] = cnt; }
    __syncthreads();
    if (t == 0) {
        double T = 0.0, C = 0.0;
#pragma unroll
        for (int w = 0; w < 8; w++) { T += st[w]; C += sc[w]; }
        out[0] = (float)(T / (C > 1.0 ? C : 1.0));
    }
}

extern "C" void kernel_launch(void* const* d_in, const int* in_sizes, int n_in,
                              void* d_out, int out_size) {
    const float2* kp = (const float2*)d_in[0];   // [B, N, 2] f32
    const int* cls = (const int*)d_in[1];        // [B, N] i32
    const int N = 512;
    const int B = in_sizes[1] / N;               // 256

    symc_partial_kernel<<<B, 256>>>(kp, cls, N);
    symc_finalize_kernel<<<1, 256>>>((float*)d_out, B);
}

// round 2
// speedup vs baseline: 1.1345x; 1.1345x over previous
#include <cuda_runtime.h>
#include <cuda_bf16.h>

// Global accumulators for the single-kernel fused reduction.
// Zero-initialized at module load; the last block resets them to zero after
// use so every graph replay sees the same initial state (deterministic).
__device__ double g_tot = 0.0;
__device__ double g_cnt = 0.0;
__device__ unsigned int g_ticket = 0u;

static constexpr float CX = 0.5f;

__device__ __forceinline__ float warp_red(float v) {
#pragma unroll
    for (int o = 16; o > 0; o >>= 1)
        v += __shfl_down_sync(0xFFFFFFFFu, v, o);
    return v;
}

// One block per batch (grid = B = 256, block = 256). N = 512 points per batch,
// so each thread handles exactly 2 points via one float4 + one int2 load.
__global__ void __launch_bounds__(256)
symc_fused_kernel(const float4* __restrict__ kp4,   // [B * N/2] pairs of points
                  const int2* __restrict__ cls2,    // [B * N/2]
                  float* __restrict__ out) {
    const int b = blockIdx.x;
    const int t = threadIdx.x;
    const int idx = b * 256 + t;  // N/2 = 256 float4/int2 per batch

    float4 p = kp4[idx];
    int2 cc = cls2[idx];

    // 3 symmetric classes x 5 moments: m, Su, Su2, Sy, Sy2  (u = x - cx)
    float m0 = 0.f, su0 = 0.f, sq0 = 0.f, sy0 = 0.f, sz0 = 0.f;
    float m1 = 0.f, su1 = 0.f, sq1 = 0.f, sy1 = 0.f, sz1 = 0.f;
    float m2 = 0.f, su2 = 0.f, sq2 = 0.f, sy2 = 0.f, sz2 = 0.f;

    {
        float u = p.x - CX, y = p.y;
        int c = cc.x;
        if (c == 0)      { m0 += 1.f; su0 += u; sq0 += u * u; sy0 += y; sz0 += y * y; }
        else if (c == 1) { m1 += 1.f; su1 += u; sq1 += u * u; sy1 += y; sz1 += y * y; }
        else if (c == 2) { m2 += 1.f; su2 += u; sq2 += u * u; sy2 += y; sz2 += y * y; }
    }
    {
        float u = p.z - CX, y = p.w;
        int c = cc.y;
        if (c == 0)      { m0 += 1.f; su0 += u; sq0 += u * u; sy0 += y; sz0 += y * y; }
        else if (c == 1) { m1 += 1.f; su1 += u; sq1 += u * u; sy1 += y; sz1 += y * y; }
        else if (c == 2) { m2 += 1.f; su2 += u; sq2 += u * u; sy2 += y; sz2 += y * y; }
    }

    // Warp reduction of all 15 accumulators
    m0 = warp_red(m0); su0 = warp_red(su0); sq0 = warp_red(sq0); sy0 = warp_red(sy0); sz0 = warp_red(sz0);
    m1 = warp_red(m1); su1 = warp_red(su1); sq1 = warp_red(sq1); sy1 = warp_red(sy1); sz1 = warp_red(sz1);
    m2 = warp_red(m2); su2 = warp_red(su2); sq2 = warp_red(sq2); sy2 = warp_red(sy2); sz2 = warp_red(sz2);

    __shared__ float s[8][15];
    const int wid = t >> 5, lid = t & 31;
    if (lid == 0) {
        s[wid][0]  = m0; s[wid][1]  = su0; s[wid][2]  = sq0; s[wid][3]  = sy0; s[wid][4]  = sz0;
        s[wid][5]  = m1; s[wid][6]  = su1; s[wid][7]  = sq1; s[wid][8]  = sy1; s[wid][9]  = sz1;
        s[wid][10] = m2; s[wid][11] = su2; s[wid][12] = sq2; s[wid][13] = sy2; s[wid][14] = sz2;
    }
    __syncthreads();

    if (t == 0) {
        double total = 0.0, cnt = 0.0;
#pragma unroll
        for (int c = 0; c < 3; c++) {
            double m = 0.0, Su = 0.0, Su2 = 0.0, Sy = 0.0, Sy2 = 0.0;
#pragma unroll
            for (int w = 0; w < 8; w++) {
                m   += (double)s[w][c * 5 + 0];
                Su  += (double)s[w][c * 5 + 1];
                Su2 += (double)s[w][c * 5 + 2];
                Sy  += (double)s[w][c * 5 + 3];
                Sy2 += (double)s[w][c * 5 + 4];
            }
            // sum_{i<j} (u_i+u_j)^2 = (m-2)*Su2 + Su^2
            // sum_{i<j} (y_i-y_j)^2 = m*Sy2 - Sy^2
            total += (m - 2.0) * Su2 + Su * Su + m * Sy2 - Sy * Sy;
            cnt += m * (m - 1.0) * 0.5;
        }

        atomicAdd(&g_tot, total);
        atomicAdd(&g_cnt, cnt);
        __threadfence();
        unsigned int ticket = atomicAdd(&g_ticket, 1u);
        if (ticket == gridDim.x - 1) {
            // Last block: all other blocks' contributions are visible.
            double T = g_tot, C = g_cnt;
            out[0] = (float)(T / (C > 1.0 ? C : 1.0));
            // Reset for the next (graph-replayed) launch.
            g_tot = 0.0;
            g_cnt = 0.0;
            g_ticket = 0u;
        }
    }
}

extern "C" void kernel_launch(void* const* d_in, const int* in_sizes, int n_in,
                              void* d_out, int out_size) {
    const float4* kp4 = (const float4*)d_in[0];  // [B, N, 2] f32 -> B*N/2 float4
    const int2* cls2 = (const int2*)d_in[1];     // [B, N] i32 -> B*N/2 int2
    const int N = 512;
    const int B = in_sizes[1] / N;               // 256

    symc_fused_kernel<<<B, 256>>>(kp4, cls2, (float*)d_out);
}

// round 3
// speedup vs baseline: 1.4975x; 1.3200x over previous
#include <cuda_runtime.h>
#include <cuda_bf16.h>

// Global accumulators. Zero at load; last block resets them after use so every
// graph replay sees identical initial state.
__device__ double g_tot = 0.0;
__device__ double g_cnt = 0.0;
__device__ unsigned int g_ticket = 0u;

static constexpr float CX = 0.5f;

__device__ __forceinline__ float warp_red(float v) {
#pragma unroll
    for (int o = 16; o > 0; o >>= 1)
        v += __shfl_down_sync(0xFFFFFFFFu, v, o);
    return v;
}

// One WARP per batch. N = 512 points/batch = 256 float4 / int2 elements.
// Each lane handles 8 stride-32 float4s (16 points) -> 16 independent loads.
// Block = 256 threads = 8 warps = 8 batches; grid = B/8 = 32 blocks.
__global__ void __launch_bounds__(256)
symc_warp_kernel(const float4* __restrict__ kp4,
                 const int2* __restrict__ cls2,
                 float* __restrict__ out, int B) {
    const int t = threadIdx.x;
    const int wid = t >> 5, lane = t & 31;
    const int b = blockIdx.x * 8 + wid;

    __shared__ double stot[8], scnt[8];

    if (b < B) {
        const int base4 = b * 256;  // N/2 float4 per batch

        float4 p[8];
        int2 c[8];
#pragma unroll
        for (int j = 0; j < 8; j++) {
            const int idx = base4 + j * 32 + lane;
            p[j] = kp4[idx];
            c[j] = cls2[idx];
        }

        // 3 symmetric classes x 5 moments: m, Su, Su2, Sy, Sy2  (u = x - cx)
        float m0 = 0.f, su0 = 0.f, sq0 = 0.f, sy0 = 0.f, sz0 = 0.f;
        float m1 = 0.f, su1 = 0.f, sq1 = 0.f, sy1 = 0.f, sz1 = 0.f;
        float m2 = 0.f, su2 = 0.f, sq2 = 0.f, sy2 = 0.f, sz2 = 0.f;

#pragma unroll
        for (int j = 0; j < 8; j++) {
            {
                float u = p[j].x - CX, y = p[j].y;
                int cc = c[j].x;
                if (cc == 0)      { m0 += 1.f; su0 += u; sq0 += u * u; sy0 += y; sz0 += y * y; }
                else if (cc == 1) { m1 += 1.f; su1 += u; sq1 += u * u; sy1 += y; sz1 += y * y; }
                else if (cc == 2) { m2 += 1.f; su2 += u; sq2 += u * u; sy2 += y; sz2 += y * y; }
            }
            {
                float u = p[j].z - CX, y = p[j].w;
                int cc = c[j].y;
                if (cc == 0)      { m0 += 1.f; su0 += u; sq0 += u * u; sy0 += y; sz0 += y * y; }
                else if (cc == 1) { m1 += 1.f; su1 += u; sq1 += u * u; sy1 += y; sz1 += y * y; }
                else if (cc == 2) { m2 += 1.f; su2 += u; sq2 += u * u; sy2 += y; sz2 += y * y; }
            }
        }

        m0 = warp_red(m0); su0 = warp_red(su0); sq0 = warp_red(sq0); sy0 = warp_red(sy0); sz0 = warp_red(sz0);
        m1 = warp_red(m1); su1 = warp_red(su1); sq1 = warp_red(sq1); sy1 = warp_red(sy1); sz1 = warp_red(sz1);
        m2 = warp_red(m2); su2 = warp_red(su2); sq2 = warp_red(sq2); sy2 = warp_red(sy2); sz2 = warp_red(sz2);

        if (lane == 0) {
            // Closed form per (batch, class):
            //   sum_{i<j} (u_i+u_j)^2 = (m-2)*Su2 + Su^2
            //   sum_{i<j} (y_i-y_j)^2 = m*Sy2 - Sy^2
            //   pairs = m*(m-1)/2
            double total =
                ((double)m0 - 2.0) * sq0 + (double)su0 * su0 + (double)m0 * sz0 - (double)sy0 * sy0
              + ((double)m1 - 2.0) * sq1 + (double)su1 * su1 + (double)m1 * sz1 - (double)sy1 * sy1
              + ((double)m2 - 2.0) * sq2 + (double)su2 * su2 + (double)m2 * sz2 - (double)sy2 * sy2;
            double cnt = 0.5 * ((double)m0 * (m0 - 1.0)
                              + (double)m1 * (m1 - 1.0)
                              + (double)m2 * (m2 - 1.0));
            stot[wid] = total;
            scnt[wid] = cnt;
        }
    } else if (lane == 0) {
        stot[wid] = 0.0;
        scnt[wid] = 0.0;
    }

    __syncthreads();

    if (t == 0) {
        double total = 0.0, cnt = 0.0;
#pragma unroll
        for (int w = 0; w < 8; w++) { total += stot[w]; cnt += scnt[w]; }

        atomicAdd(&g_tot, total);
        atomicAdd(&g_cnt, cnt);
        __threadfence();
        unsigned int ticket = atomicAdd(&g_ticket, 1u);
        if (ticket == gridDim.x - 1) {
            double T = g_tot, C = g_cnt;
            out[0] = (float)(T / (C > 1.0 ? C : 1.0));
            g_tot = 0.0;
            g_cnt = 0.0;
            g_ticket = 0u;
        }
    }
}

extern "C" void kernel_launch(void* const* d_in, const int* in_sizes, int n_in,
                              void* d_out, int out_size) {
    const float4* kp4 = (const float4*)d_in[0];  // [B, N, 2] f32
    const int2* cls2 = (const int2*)d_in[1];     // [B, N] i32
    const int N = 512;
    const int B = in_sizes[1] / N;               // 256
    const int grid = (B + 7) / 8;                // 8 batches (warps) per block

    symc_warp_kernel<<<grid, 256>>>(kp4, cls2, (float*)d_out, B);
}